// round 10
// baseline (speedup 1.0000x reference)
#include <cuda_runtime.h>
#include <math.h>
#include <stdint.h>

// Fused single-step GRU(hidden=1) + Linear(1,1).
// Input per row (65 fp32): [h0, x0..x63]. 524288 rows.
//
// R8: warp-autonomous cp.async double-buffered pipelines, 8 warps/CTA,
// 16-row warp tiles. R6/R7 plateaued at DRAM=67% with 12 warps/SM and
// lumpy 8.3 KB bursts; this doubles the concurrent request streams (24
// warps/SM) at the same in-flight bytes for a smoother DRAM queue.
// Each row is computed by a lane pair (L: k=0..31, L+16: k=32..63) and
// combined with one shfl_xor(16).

#define NTHREADS       256
#define NWARPS         8
#define WT_ROWS        16                        // rows per warp-tile
#define FDIM           65
#define WT_FLOATS      (WT_ROWS * FDIM)          // 1040
#define WT_VEC4        (WT_FLOATS / 4)           // 260 = 8*32 + 4

// dynamic smem: 8 warps * 2 buffers * 1040 floats | W(192) | P(12)
#define SMEM_FLOATS    (NWARPS * 2 * WT_FLOATS + 192 + 12)

__device__ __forceinline__ void cp_async16(uint32_t saddr, const void* gptr) {
    asm volatile("cp.async.cg.shared.global [%0], [%1], 16;\n"
                 :: "r"(saddr), "l"(gptr));
}
__device__ __forceinline__ void cp_async4(uint32_t saddr, const void* gptr) {
    asm volatile("cp.async.ca.shared.global [%0], [%1], 4;\n"
                 :: "r"(saddr), "l"(gptr));
}
__device__ __forceinline__ void cp_commit() {
    asm volatile("cp.async.commit_group;\n");
}
template <int N>
__device__ __forceinline__ void cp_wait() {
    asm volatile("cp.async.wait_group %0;\n" :: "n"(N));
}

__global__ void __launch_bounds__(NTHREADS, 3)
gru_fused_kernel(const float* __restrict__ in,
                 const float* __restrict__ Wih,   // [3,64]
                 const float* __restrict__ Whh,   // [3,1]
                 const float* __restrict__ bih,   // [3]
                 const float* __restrict__ bhh,   // [3]
                 const float* __restrict__ wout,  // [1,1]
                 const float* __restrict__ bout,  // [1]
                 float* __restrict__ out,
                 int rows, int nWTiles)
{
    extern __shared__ __align__(16) float sm[];
    float* smW = sm + NWARPS * 2 * WT_FLOATS;
    float* smP = smW + 192;

    const int tid  = threadIdx.x;
    const int wid  = tid >> 5;
    const int lane = tid & 31;

    // ---- params into smem (once per CTA) ----
    if (tid < 48)
        reinterpret_cast<float4*>(smW)[tid] =
            reinterpret_cast<const float4*>(Wih)[tid];
    if (tid < 3) {
        smP[tid]     = Whh[tid];
        smP[3 + tid] = bih[tid];
        smP[6 + tid] = bhh[tid];
    }
    if (tid == 0) { smP[9] = wout[0]; smP[10] = bout[0]; }

    float* myBuf0 = sm + (wid * 2 + 0) * WT_FLOATS;
    float* myBuf1 = sm + (wid * 2 + 1) * WT_FLOATS;

    // ---- per-warp prefetch of one 16-row tile into buffer b ----
    auto prefetch = [&](int wt, int b) {
        float* buf = b ? myBuf1 : myBuf0;
        const uint32_t sbase = (uint32_t)__cvta_generic_to_shared(buf);
        const float* src = in + (size_t)wt * WT_FLOATS;
        if ((wt + 1) * WT_ROWS <= rows) {                   // full tile
            #pragma unroll
            for (int i = 0; i < 9; i++) {
                const int idx = lane + i * 32;
                if (idx < WT_VEC4)                          // i=8: lanes 0-3
                    cp_async16(sbase + (uint32_t)idx * 16u, src + idx * 4);
            }
        } else {                                            // partial tail
            const int nflt = (rows - wt * WT_ROWS) * FDIM;
            for (int i = lane; i < nflt; i += 32)
                cp_async4(sbase + (uint32_t)i * 4u, src + i);
        }
    };

    const int warpStride = (int)gridDim.x * NWARPS;
    const int w0 = (int)blockIdx.x * NWARPS + wid;

    if (w0 < nWTiles) prefetch(w0, 0);
    cp_commit();

    // single block barrier: weights/params visible to all warps
    __syncthreads();

    // lane pair split: lanes 0-15 handle k=0..31 of row (lane&15),
    // lanes 16-31 handle k=32..63 of the same row.
    const int rowInTile = lane & 15;
    const int koff      = (lane >> 4) << 5;     // 0 or 32

    int bi = 0;
    for (int wt = w0; wt < nWTiles; wt += warpStride) {
        const int nxt = wt + warpStride;
        if (nxt < nWTiles) prefetch(nxt, bi ^ 1);
        cp_commit();            // empty group ok on last iteration
        cp_wait<1>();           // this warp's current tile complete
        __syncwarp();

        const float* row = (bi ? myBuf1 : myBuf0) + rowInTile * FDIM;
        const float h = row[0];

        float s0 = 0.f, s1 = 0.f, s2 = 0.f;
        #pragma unroll
        for (int k = 0; k < 32; k += 4) {
            const float4 w0v = *reinterpret_cast<const float4*>(smW + koff + k);
            const float4 w1v = *reinterpret_cast<const float4*>(smW + 64 + koff + k);
            const float4 w2v = *reinterpret_cast<const float4*>(smW + 128 + koff + k);
            const float x0 = row[1 + koff + k];
            const float x1 = row[2 + koff + k];
            const float x2 = row[3 + koff + k];
            const float x3 = row[4 + koff + k];
            s0 = fmaf(w0v.x, x0, fmaf(w0v.y, x1, fmaf(w0v.z, x2, fmaf(w0v.w, x3, s0))));
            s1 = fmaf(w1v.x, x0, fmaf(w1v.y, x1, fmaf(w1v.z, x2, fmaf(w1v.w, x3, s1))));
            s2 = fmaf(w2v.x, x0, fmaf(w2v.y, x1, fmaf(w2v.z, x2, fmaf(w2v.w, x3, s2))));
        }
        // combine lane-pair partials (L <-> L+16)
        s0 += __shfl_xor_sync(0xffffffffu, s0, 16);
        s1 += __shfl_xor_sync(0xffffffffu, s1, 16);
        s2 += __shfl_xor_sync(0xffffffffu, s2, 16);

        const float whh_r = smP[0], whh_z = smP[1], whh_n = smP[2];
        const float bih_r = smP[3], bih_z = smP[4], bih_n = smP[5];
        const float bhh_r = smP[6], bhh_z = smP[7], bhh_n = smP[8];
        const float w_o   = smP[9], b_o   = smP[10];

        const float gr  = s0 + bih_r + fmaf(h, whh_r, bhh_r);
        const float gz  = s1 + bih_z + fmaf(h, whh_z, bhh_z);
        const float ghn = fmaf(h, whh_n, bhh_n);

        const float r = 1.f / (1.f + expf(-gr));
        const float z = 1.f / (1.f + expf(-gz));
        const float n = tanhf(s2 + bih_n + r * ghn);
        const float hn = fmaf(1.f - z, n, z * h);

        const int myRow = wt * WT_ROWS + rowInTile;
        if (lane < 16 && myRow < rows)
            out[myRow] = fmaf(hn, w_o, b_o);

        __syncwarp();           // all lanes done reading before refill
        bi ^= 1;
    }
}

extern "C" void kernel_launch(void* const* d_in, const int* in_sizes, int n_in,
                              void* d_out, int out_size)
{
    const float* in   = (const float*)d_in[0];   // [B, N, 65]
    const float* Wih  = (const float*)d_in[1];   // [3, 64]
    const float* Whh  = (const float*)d_in[2];   // [3, 1]
    const float* bih  = (const float*)d_in[3];   // [3]
    const float* bhh  = (const float*)d_in[4];   // [3]
    const float* wout = (const float*)d_in[5];   // [1, 1]
    const float* bout = (const float*)d_in[6];   // [1]
    float* out = (float*)d_out;

    const int rows    = out_size;                // 524288
    const int nWTiles = (rows + WT_ROWS - 1) / WT_ROWS;   // 32768

    const int smemBytes = SMEM_FLOATS * (int)sizeof(float);   // ~65.8 KB
    cudaFuncSetAttribute(gru_fused_kernel,
                         cudaFuncAttributeMaxDynamicSharedMemorySize, smemBytes);

    // persistent grid: 3 CTAs/SM on 148 SMs (3*65.8KB < 228KB carveout)
    int grid = 444;
    const int maxGrid = (nWTiles + NWARPS - 1) / NWARPS;
    if (grid > maxGrid) grid = maxGrid;

    gru_fused_kernel<<<grid, NTHREADS, smemBytes>>>(in, Wih, Whh, bih, bhh,
                                                    wout, bout, out,
                                                    rows, nWTiles);
}

// round 13
// speedup vs baseline: 1.0077x; 1.0077x over previous
#include <cuda_runtime.h>
#include <math.h>
#include <stdint.h>

// Fused single-step GRU(hidden=1) + Linear(1,1).
// Input per row (65 fp32): [h0, x0..x63]. 524288 rows.
//
// R11: warp-autonomous cp.async pipelines, 8 warps/CTA, 16-row tiles,
// THREE stages (wait_group<2>). R6/R7/R8 all equilibrated at DRAM~66%
// with exactly one tile in flight per warp (~100 KB/SM); Little's law
// pinned BW at inflight/L. This holds 2 tiles in flight per warp
// (133 KB/SM at 2 CTAs/SM) so demand never gaps while a warp computes.
// Lane pair split: L handles k=0..31, L+16 handles k=32..63 of row L&15;
// combined with one shfl_xor(16).

#define NTHREADS       256
#define NWARPS         8
#define NSTAGES        3
#define WT_ROWS        16                        // rows per warp-tile
#define FDIM           65
#define WT_FLOATS      (WT_ROWS * FDIM)          // 1040
#define WT_VEC4        (WT_FLOATS / 4)           // 260 = 8*32 + 4

// dynamic smem: 8 warps * 3 buffers * 1040 floats | W(192) | P(12)
#define SMEM_FLOATS    (NWARPS * NSTAGES * WT_FLOATS + 192 + 12)

__device__ __forceinline__ void cp_async16(uint32_t saddr, const void* gptr) {
    asm volatile("cp.async.cg.shared.global [%0], [%1], 16;\n"
                 :: "r"(saddr), "l"(gptr));
}
__device__ __forceinline__ void cp_async4(uint32_t saddr, const void* gptr) {
    asm volatile("cp.async.ca.shared.global [%0], [%1], 4;\n"
                 :: "r"(saddr), "l"(gptr));
}
__device__ __forceinline__ void cp_commit() {
    asm volatile("cp.async.commit_group;\n");
}
template <int N>
__device__ __forceinline__ void cp_wait() {
    asm volatile("cp.async.wait_group %0;\n" :: "n"(N));
}

__global__ void __launch_bounds__(NTHREADS, 2)
gru_fused_kernel(const float* __restrict__ in,
                 const float* __restrict__ Wih,   // [3,64]
                 const float* __restrict__ Whh,   // [3,1]
                 const float* __restrict__ bih,   // [3]
                 const float* __restrict__ bhh,   // [3]
                 const float* __restrict__ wout,  // [1,1]
                 const float* __restrict__ bout,  // [1]
                 float* __restrict__ out,
                 int rows, int nWTiles)
{
    extern __shared__ __align__(16) float sm[];
    float* smW = sm + NWARPS * NSTAGES * WT_FLOATS;
    float* smP = smW + 192;

    const int tid  = threadIdx.x;
    const int wid  = tid >> 5;
    const int lane = tid & 31;

    // ---- params into smem (once per CTA) ----
    if (tid < 48)
        reinterpret_cast<float4*>(smW)[tid] =
            reinterpret_cast<const float4*>(Wih)[tid];
    if (tid < 3) {
        smP[tid]     = Whh[tid];
        smP[3 + tid] = bih[tid];
        smP[6 + tid] = bhh[tid];
    }
    if (tid == 0) { smP[9] = wout[0]; smP[10] = bout[0]; }

    float* myBufs = sm + wid * NSTAGES * WT_FLOATS;

    // ---- per-warp prefetch of one 16-row tile into stage s ----
    auto prefetch = [&](int wt, int s) {
        float* buf = myBufs + s * WT_FLOATS;
        const uint32_t sbase = (uint32_t)__cvta_generic_to_shared(buf);
        const float* src = in + (size_t)wt * WT_FLOATS;
        if ((wt + 1) * WT_ROWS <= rows) {                   // full tile
            #pragma unroll
            for (int i = 0; i < 9; i++) {
                const int idx = lane + i * 32;
                if (idx < WT_VEC4)                          // i=8: lanes 0-3
                    cp_async16(sbase + (uint32_t)idx * 16u, src + idx * 4);
            }
        } else {                                            // partial tail
            const int nflt = (rows - wt * WT_ROWS) * FDIM;
            for (int i = lane; i < nflt; i += 32)
                cp_async4(sbase + (uint32_t)i * 4u, src + i);
        }
    };

    const int warpStride = (int)gridDim.x * NWARPS;
    const int w0 = (int)blockIdx.x * NWARPS + wid;

    // prologue: stages 0 and 1 in flight
    if (w0 < nWTiles) prefetch(w0, 0);
    cp_commit();
    if (w0 + warpStride < nWTiles) prefetch(w0 + warpStride, 1);
    cp_commit();

    // single block barrier: weights/params visible to all warps
    __syncthreads();

    // lane pair split: lanes 0-15 handle k=0..31 of row (lane&15),
    // lanes 16-31 handle k=32..63 of the same row.
    const int rowInTile = lane & 15;
    const int koff      = (lane >> 4) << 5;     // 0 or 32

    int st = 0;
    for (int wt = w0; wt < nWTiles; wt += warpStride) {
        const int nxt2 = wt + 2 * warpStride;
        const int s2 = (st + 2 >= NSTAGES) ? st + 2 - NSTAGES : st + 2;
        if (nxt2 < nWTiles) prefetch(nxt2, s2);
        cp_commit();            // empty group ok near the tail
        cp_wait<2>();           // tile wt's group complete; 2 newest pending
        __syncwarp();

        const float* row = myBufs + st * WT_FLOATS + rowInTile * FDIM;
        const float h = row[0];

        float s0 = 0.f, s1 = 0.f, s2a = 0.f;
        #pragma unroll
        for (int k = 0; k < 32; k += 4) {
            const float4 w0v = *reinterpret_cast<const float4*>(smW + koff + k);
            const float4 w1v = *reinterpret_cast<const float4*>(smW + 64 + koff + k);
            const float4 w2v = *reinterpret_cast<const float4*>(smW + 128 + koff + k);
            const float x0 = row[1 + koff + k];
            const float x1 = row[2 + koff + k];
            const float x2 = row[3 + koff + k];
            const float x3 = row[4 + koff + k];
            s0  = fmaf(w0v.x, x0, fmaf(w0v.y, x1, fmaf(w0v.z, x2, fmaf(w0v.w, x3, s0))));
            s1  = fmaf(w1v.x, x0, fmaf(w1v.y, x1, fmaf(w1v.z, x2, fmaf(w1v.w, x3, s1))));
            s2a = fmaf(w2v.x, x0, fmaf(w2v.y, x1, fmaf(w2v.z, x2, fmaf(w2v.w, x3, s2a))));
        }
        // combine lane-pair partials (L <-> L+16)
        s0  += __shfl_xor_sync(0xffffffffu, s0, 16);
        s1  += __shfl_xor_sync(0xffffffffu, s1, 16);
        s2a += __shfl_xor_sync(0xffffffffu, s2a, 16);

        const float whh_r = smP[0], whh_z = smP[1], whh_n = smP[2];
        const float bih_r = smP[3], bih_z = smP[4], bih_n = smP[5];
        const float bhh_r = smP[6], bhh_z = smP[7], bhh_n = smP[8];
        const float w_o   = smP[9], b_o   = smP[10];

        const float gr  = s0 + bih_r + fmaf(h, whh_r, bhh_r);
        const float gz  = s1 + bih_z + fmaf(h, whh_z, bhh_z);
        const float ghn = fmaf(h, whh_n, bhh_n);

        const float r = 1.f / (1.f + expf(-gr));
        const float z = 1.f / (1.f + expf(-gz));
        const float n = tanhf(s2a + bih_n + r * ghn);
        const float hn = fmaf(1.f - z, n, z * h);

        const int myRow = wt * WT_ROWS + rowInTile;
        if (lane < 16 && myRow < rows)
            out[myRow] = fmaf(hn, w_o, b_o);

        __syncwarp();           // all lanes done reading before this buffer
        st = (st + 1 >= NSTAGES) ? 0 : st + 1;   // is refilled (2 iters later)
    }
}

extern "C" void kernel_launch(void* const* d_in, const int* in_sizes, int n_in,
                              void* d_out, int out_size)
{
    const float* in   = (const float*)d_in[0];   // [B, N, 65]
    const float* Wih  = (const float*)d_in[1];   // [3, 64]
    const float* Whh  = (const float*)d_in[2];   // [3, 1]
    const float* bih  = (const float*)d_in[3];   // [3]
    const float* bhh  = (const float*)d_in[4];   // [3]
    const float* wout = (const float*)d_in[5];   // [1, 1]
    const float* bout = (const float*)d_in[6];   // [1]
    float* out = (float*)d_out;

    const int rows    = out_size;                // 524288
    const int nWTiles = (rows + WT_ROWS - 1) / WT_ROWS;   // 32768

    const int smemBytes = SMEM_FLOATS * (int)sizeof(float);   // ~100.6 KB
    cudaFuncSetAttribute(gru_fused_kernel,
                         cudaFuncAttributeMaxDynamicSharedMemorySize, smemBytes);

    // persistent grid: 2 CTAs/SM on 148 SMs (2*100.6KB < 228KB carveout)
    int grid = 296;
    const int maxGrid = (nWTiles + NWARPS - 1) / NWARPS;
    if (grid > maxGrid) grid = maxGrid;

    gru_fused_kernel<<<grid, NTHREADS, smemBytes>>>(in, Wih, Whh, bih, bhh,
                                                    wout, bout, out,
                                                    rows, nWTiles);
}

// round 16
// speedup vs baseline: 1.0837x; 1.0755x over previous
#include <cuda_runtime.h>
#include <math.h>
#include <stdint.h>

// Fused single-step GRU(hidden=1) + Linear(1,1).
// Input per row (65 fp32): [h0, x0..x63]. 524288 rows.
//
// R14b: R8 base (8 warps/CTA, 16-row tiles, 2-stage cp.async, 3 CTAs/SM)
// plus two compute-side fixes from the R13 L1tex recount:
//  (1) upper-half lanes iterate k rotated by 16 -> scalar LDS bank sets
//      of the two half-warps are disjoint (was a 2-way conflict: 64 wf
//      instead of 32 per iteration);
//  (2) gates via __expf (HW MUFU.EX2/RCP, ~1e-6 rel err) instead of the
//      long software expf/tanhf chains. (tanh.approx rejected: 3 gates
//      x 5e-4 abs err stacks too close to the 1e-3 gate.)
// Theory: iterations are compute/L1tex-paced, not latency-limited; cut
// the pacing cost and DRAM busy rises.

#define NTHREADS       256
#define NWARPS         8
#define WT_ROWS        16                        // rows per warp-tile
#define FDIM           65
#define WT_FLOATS      (WT_ROWS * FDIM)          // 1040
#define WT_VEC4        (WT_FLOATS / 4)           // 260 = 8*32 + 4

// dynamic smem: 8 warps * 2 buffers * 1040 floats | W(192) | P(12)
#define SMEM_FLOATS    (NWARPS * 2 * WT_FLOATS + 192 + 12)

__device__ __forceinline__ void cp_async16(uint32_t saddr, const void* gptr) {
    asm volatile("cp.async.cg.shared.global [%0], [%1], 16;\n"
                 :: "r"(saddr), "l"(gptr));
}
__device__ __forceinline__ void cp_async4(uint32_t saddr, const void* gptr) {
    asm volatile("cp.async.ca.shared.global [%0], [%1], 4;\n"
                 :: "r"(saddr), "l"(gptr));
}
__device__ __forceinline__ void cp_commit() {
    asm volatile("cp.async.commit_group;\n");
}
template <int N>
__device__ __forceinline__ void cp_wait() {
    asm volatile("cp.async.wait_group %0;\n" :: "n"(N));
}
__device__ __forceinline__ float fast_sigmoid(float x) {
    return 1.0f / (1.0f + __expf(-x));           // MUFU.EX2 + MUFU.RCP path
}
__device__ __forceinline__ float fast_tanh(float x) {
    return fmaf(2.0f, 1.0f / (1.0f + __expf(-2.0f * x)), -1.0f);
}

__global__ void __launch_bounds__(NTHREADS, 3)
gru_fused_kernel(const float* __restrict__ in,
                 const float* __restrict__ Wih,   // [3,64]
                 const float* __restrict__ Whh,   // [3,1]
                 const float* __restrict__ bih,   // [3]
                 const float* __restrict__ bhh,   // [3]
                 const float* __restrict__ wout,  // [1,1]
                 const float* __restrict__ bout,  // [1]
                 float* __restrict__ out,
                 int rows, int nWTiles)
{
    extern __shared__ __align__(16) float sm[];
    float* smW = sm + NWARPS * 2 * WT_FLOATS;
    float* smP = smW + 192;

    const int tid  = threadIdx.x;
    const int wid  = tid >> 5;
    const int lane = tid & 31;

    // ---- params into smem (once per CTA) ----
    if (tid < 48)
        reinterpret_cast<float4*>(smW)[tid] =
            reinterpret_cast<const float4*>(Wih)[tid];
    if (tid < 3) {
        smP[tid]     = Whh[tid];
        smP[3 + tid] = bih[tid];
        smP[6 + tid] = bhh[tid];
    }
    if (tid == 0) { smP[9] = wout[0]; smP[10] = bout[0]; }

    float* myBuf0 = sm + (wid * 2 + 0) * WT_FLOATS;
    float* myBuf1 = sm + (wid * 2 + 1) * WT_FLOATS;

    // ---- per-warp prefetch of one 16-row tile into buffer b ----
    auto prefetch = [&](int wt, int b) {
        float* buf = b ? myBuf1 : myBuf0;
        const uint32_t sbase = (uint32_t)__cvta_generic_to_shared(buf);
        const float* src = in + (size_t)wt * WT_FLOATS;
        if ((wt + 1) * WT_ROWS <= rows) {                   // full tile
            #pragma unroll
            for (int i = 0; i < 9; i++) {
                const int idx = lane + i * 32;
                if (idx < WT_VEC4)                          // i=8: lanes 0-3
                    cp_async16(sbase + (uint32_t)idx * 16u, src + idx * 4);
            }
        } else {                                            // partial tail
            const int nflt = (rows - wt * WT_ROWS) * FDIM;
            for (int i = lane; i < nflt; i += 32)
                cp_async4(sbase + (uint32_t)i * 4u, src + i);
        }
    };

    const int warpStride = (int)gridDim.x * NWARPS;
    const int w0 = (int)blockIdx.x * NWARPS + wid;

    if (w0 < nWTiles) prefetch(w0, 0);
    cp_commit();

    // single block barrier: weights/params visible to all warps
    __syncthreads();

    // lane pair split: lanes 0-15 handle k=0..31 of row (lane&15),
    // lanes 16-31 handle k=32..63 of the same row.
    const int rowInTile = lane & 15;
    const bool upper    = (lane >= 16);
    const int koff      = upper ? 32 : 0;

    int bi = 0;
    for (int wt = w0; wt < nWTiles; wt += warpStride) {
        const int nxt = wt + warpStride;
        if (nxt < nWTiles) prefetch(nxt, bi ^ 1);
        cp_commit();            // empty group ok on last iteration
        cp_wait<1>();           // this warp's current tile complete
        __syncwarp();

        const float* row = (bi ? myBuf1 : myBuf0) + rowInTile * FDIM;
        const float h = row[0];

        float s0 = 0.f, s1 = 0.f, s2 = 0.f;
        #pragma unroll
        for (int k = 0; k < 32; k += 4) {
            // upper half iterates k rotated by 16 so the two half-warps'
            // scalar LDS hit disjoint bank sets (no 2-way conflict).
            const int kk   = upper ? ((k + 16) & 31) : k;
            const int base = koff + kk;
            const float4 w0v = *reinterpret_cast<const float4*>(smW + base);
            const float4 w1v = *reinterpret_cast<const float4*>(smW + 64 + base);
            const float4 w2v = *reinterpret_cast<const float4*>(smW + 128 + base);
            const float x0 = row[1 + base];
            const float x1 = row[2 + base];
            const float x2 = row[3 + base];
            const float x3 = row[4 + base];
            s0 = fmaf(w0v.x, x0, fmaf(w0v.y, x1, fmaf(w0v.z, x2, fmaf(w0v.w, x3, s0))));
            s1 = fmaf(w1v.x, x0, fmaf(w1v.y, x1, fmaf(w1v.z, x2, fmaf(w1v.w, x3, s1))));
            s2 = fmaf(w2v.x, x0, fmaf(w2v.y, x1, fmaf(w2v.z, x2, fmaf(w2v.w, x3, s2))));
        }
        // combine lane-pair partials (L <-> L+16)
        s0 += __shfl_xor_sync(0xffffffffu, s0, 16);
        s1 += __shfl_xor_sync(0xffffffffu, s1, 16);
        s2 += __shfl_xor_sync(0xffffffffu, s2, 16);

        const float whh_r = smP[0], whh_z = smP[1], whh_n = smP[2];
        const float bih_r = smP[3], bih_z = smP[4], bih_n = smP[5];
        const float bhh_r = smP[6], bhh_z = smP[7], bhh_n = smP[8];
        const float w_o   = smP[9], b_o   = smP[10];

        const float gr  = s0 + bih_r + fmaf(h, whh_r, bhh_r);
        const float gz  = s1 + bih_z + fmaf(h, whh_z, bhh_z);
        const float ghn = fmaf(h, whh_n, bhh_n);

        const float r = fast_sigmoid(gr);
        const float z = fast_sigmoid(gz);
        const float n = fast_tanh(s2 + bih_n + r * ghn);
        const float hn = fmaf(1.f - z, n, z * h);

        const int myRow = wt * WT_ROWS + rowInTile;
        if (lane < 16 && myRow < rows)
            out[myRow] = fmaf(hn, w_o, b_o);

        __syncwarp();           // all lanes done reading before refill
        bi ^= 1;
    }
}

extern "C" void kernel_launch(void* const* d_in, const int* in_sizes, int n_in,
                              void* d_out, int out_size)
{
    const float* in   = (const float*)d_in[0];   // [B, N, 65]
    const float* Wih  = (const float*)d_in[1];   // [3, 64]
    const float* Whh  = (const float*)d_in[2];   // [3, 1]
    const float* bih  = (const float*)d_in[3];   // [3]
    const float* bhh  = (const float*)d_in[4];   // [3]
    const float* wout = (const float*)d_in[5];   // [1, 1]
    const float* bout = (const float*)d_in[6];   // [1]
    float* out = (float*)d_out;

    const int rows    = out_size;                // 524288
    const int nWTiles = (rows + WT_ROWS - 1) / WT_ROWS;   // 32768

    const int smemBytes = SMEM_FLOATS * (int)sizeof(float);   // ~65.8 KB
    cudaFuncSetAttribute(gru_fused_kernel,
                         cudaFuncAttributeMaxDynamicSharedMemorySize, smemBytes);

    // persistent grid: 3 CTAs/SM on 148 SMs (3*65.8KB < 228KB carveout)
    int grid = 444;
    const int maxGrid = (nWTiles + NWARPS - 1) / NWARPS;
    if (grid > maxGrid) grid = maxGrid;

    gru_fused_kernel<<<grid, NTHREADS, smemBytes>>>(in, Wih, Whh, bih, bhh,
                                                    wout, bout, out,
                                                    rows, nWTiles);
}